// round 14
// baseline (speedup 1.0000x reference)
#include <cuda_runtime.h>
#include <cuda_bf16.h>
#include <cuda_fp16.h>
#include <cstdint>

#define N_NODES 100000
#define N_EDGES 1600000
#define IN_CH   128
#define TYPE_EMB 32
#define FEAT    160
#define OUT_CH  128
#define N_REL   8
#define N_BASES 8
#define NSLOT   9                 // slot 0 = root, 1..8 = relations
#define KW      192               // padded K per slot (3 x 64)
#define ZLEN    (NSLOT * OUT_CH)  // 1152 halves per node
#define NKEY    (N_NODES * N_REL)        // 800000
#define NSCANBLK ((NKEY + 1023) / 1024)  // 782
#define NTILE2  ((N_NODES + 255) / 256)  // 391

// Arch-feature gate: tcgen05 only exists on the 'a' targets.
#if defined(__CUDA_ARCH_FEAT_SM103_ALL) || defined(__CUDA_ARCH_FEAT_SM100_ALL) || \
    defined(__CUDA_ARCH_FEAT_SM101_ALL) || \
    (defined(__CUDA_ARCH_SPECIFIC__) && (__CUDA_ARCH_SPECIFIC__ >= 1000))
#define HAS_TCGEN05 1
#else
#define HAS_TCGEN05 0
#endif

// ---------------- device scratch ----------------
__device__ __half g_h16[(size_t)N_NODES * FEAT];       // fp16 h (32MB, L2-resident)
__device__ __half g_Z[(size_t)N_NODES * ZLEN];         // fp16 transformed slots (230MB)
__device__ __half g_Wt[NSLOT * OUT_CH * KW];           // W^T fp16 [slot][o][k], k padded to 192
__device__ int g_mma_ok;

// CSR scratch
__device__ int g_hist[NKEY];
__device__ int g_rowptr[NKEY + 1];
__device__ int g_cursor[NKEY];
__device__ int g_aux[NSCANBLK];
__device__ int g_auxs[NSCANBLK];
__device__ int g_esrc[N_EDGES];

// ================= PTX helpers =================
__device__ __forceinline__ uint32_t smem_u32(const void* p) {
    uint32_t a;
    asm("{ .reg .u64 t; cvta.to.shared.u64 t, %1; cvt.u32.u64 %0, t; }" : "=r"(a) : "l"(p));
    return a;
}
__device__ __forceinline__ void cp16(uint32_t smem, const void* g, uint32_t sz) {
    asm volatile("cp.async.cg.shared.global [%0], [%1], 16, %2;"
                 :: "r"(smem), "l"(g), "r"(sz) : "memory");
}
#define CP_COMMIT() asm volatile("cp.async.commit_group;" ::: "memory")
#define CP_WAIT0()  asm volatile("cp.async.wait_group 0;" ::: "memory")
#define CP_WAIT1()  asm volatile("cp.async.wait_group 1;" ::: "memory")

#define MBARRIER_INIT(addr, cnt) \
    asm volatile("mbarrier.init.shared.b64 [%0], %1;" :: "r"((uint32_t)(addr)), "r"((uint32_t)(cnt)) : "memory")
#define MBARRIER_INVAL(addr) \
    asm volatile("mbarrier.inval.shared.b64 [%0];" :: "r"((uint32_t)(addr)) : "memory")
#define MBARRIER_WAIT_PARITY(mbar_smem_addr, phase_parity) do { \
    uint32_t _mbar = (uint32_t)(mbar_smem_addr); \
    uint32_t _parity = (uint32_t)(phase_parity); \
    uint32_t _done; \
    asm volatile( \
        "{\n\t.reg .pred p;\n\t" \
        "mbarrier.try_wait.parity.acquire.cta.shared::cta.b64 p, [%1], %2;\n\t" \
        "selp.b32 %0, 1, 0, p;\n\t}" \
        : "=r"(_done) : "r"(_mbar), "r"(_parity) : "memory"); \
    if (!_done) { \
        asm volatile( \
            "{\n\t.reg .pred P1;\n\t" \
            "WAIT_LOOP_%=:\n\t" \
            "mbarrier.try_wait.parity.acquire.cta.shared::cta.b64 P1, [%0], %1, 0x989680;\n\t" \
            "@P1 bra.uni WAIT_DONE_%=;\n\t" \
            "bra.uni WAIT_LOOP_%=;\n\t" \
            "WAIT_DONE_%=:\n\t}" \
            :: "r"(_mbar), "r"(_parity) : "memory"); \
    } \
} while(0)

#if HAS_TCGEN05
__device__ __forceinline__ uint32_t elect_one() {
    uint32_t pred;
    asm volatile("{\n\t.reg .pred p;\n\telect.sync _|p, 0xFFFFFFFF;\n\tselp.b32 %0, 1, 0, p;\n\t}" : "=r"(pred));
    return pred;
}
#define TCGEN05_ALLOC(smem_addr, nCols) \
    asm volatile("tcgen05.alloc.cta_group::1.sync.aligned.shared::cta.b32 [%0], %1;" \
        :: "r"((uint32_t)(smem_addr)), "r"((uint32_t)(nCols)) : "memory")
#define TCGEN05_DEALLOC(tmem_addr, nCols) \
    asm volatile("tcgen05.dealloc.cta_group::1.sync.aligned.b32 %0, %1;" :: "r"(tmem_addr), "r"((uint32_t)(nCols)))
#define TCGEN05_RELINQ() \
    asm volatile("tcgen05.relinquish_alloc_permit.cta_group::1.sync.aligned;")
#define TCGEN05_COMMIT(mbar) \
    asm volatile("tcgen05.commit.cta_group::1.mbarrier::arrive::one.shared::cluster.b64 [%0];" \
        :: "r"((uint32_t)(mbar)) : "memory")
#define TCGEN05_FENCE_AFTER()  asm volatile("tcgen05.fence::after_thread_sync;" ::: "memory")
#define TCGEN05_FENCE_BEFORE() asm volatile("tcgen05.fence::before_thread_sync;" ::: "memory")
#define TCGEN05_WAIT_LD() asm volatile("tcgen05.wait::ld.sync.aligned;" ::: "memory")
#define TCGEN05_LD_32X32B_X32(r, tmem_addr) \
    asm volatile( \
        "tcgen05.ld.sync.aligned.32x32b.x32.b32 " \
        "{%0, %1, %2, %3, %4, %5, %6, %7, " \
        " %8, %9, %10, %11, %12, %13, %14, %15, " \
        " %16, %17, %18, %19, %20, %21, %22, %23, " \
        " %24, %25, %26, %27, %28, %29, %30, %31}, [%32];" \
        : "=r"((r)[0]),  "=r"((r)[1]),  "=r"((r)[2]),  "=r"((r)[3]), \
          "=r"((r)[4]),  "=r"((r)[5]),  "=r"((r)[6]),  "=r"((r)[7]), \
          "=r"((r)[8]),  "=r"((r)[9]),  "=r"((r)[10]), "=r"((r)[11]), \
          "=r"((r)[12]), "=r"((r)[13]), "=r"((r)[14]), "=r"((r)[15]), \
          "=r"((r)[16]), "=r"((r)[17]), "=r"((r)[18]), "=r"((r)[19]), \
          "=r"((r)[20]), "=r"((r)[21]), "=r"((r)[22]), "=r"((r)[23]), \
          "=r"((r)[24]), "=r"((r)[25]), "=r"((r)[26]), "=r"((r)[27]), \
          "=r"((r)[28]), "=r"((r)[29]), "=r"((r)[30]), "=r"((r)[31]) \
        : "r"(tmem_addr))

static constexpr uint64_t SMEM_DESC_BASE_SW128 =
    (uint64_t(2)  << 61) | (uint64_t(1) << 46) | (uint64_t(64) << 32) | (uint64_t(1) << 16);
#define MAKE_SMEM_DESC(base_addr) (SMEM_DESC_BASE_SW128 | ((uint64_t)((base_addr) >> 4) & 0x3FFF))

// idesc: dtype=F32, atype=F16, btype=F16, N=128, M=128 (kind::f16)
#define MMA_IDESC 0x8200010u

__device__ __forceinline__ void mma_f16_ss(uint32_t d, uint64_t a_desc, uint64_t b_desc, bool acc) {
    uint32_t en = acc ? 1u : 0u;
    asm volatile(
        "{\n\t.reg .pred p;\n\t"
        "setp.ne.u32 p, %5, 0;\n\t"
        "tcgen05.mma.cta_group::1.kind::f16 [%0], %1, %2, %3, {%4, %4, %4, %4}, p;\n\t"
        "}"
        :: "r"(d), "l"(a_desc), "l"(b_desc), "r"(MMA_IDESC), "r"(0u), "r"(en)
        : "memory");
}
#endif  // HAS_TCGEN05

// ---------------- CSR pipeline ----------------
__global__ void k_zero_hist() {
    int i = blockIdx.x * blockDim.x + threadIdx.x;
    if (i < NKEY) g_hist[i] = 0;
}

__global__ void k_hist(const int* __restrict__ edge_index,
                       const int* __restrict__ edge_type) {
    int e = blockIdx.x * blockDim.x + threadIdx.x;
    if (e >= N_EDGES) return;
    int dst = edge_index[N_EDGES + e];
    int r   = edge_type[e];
    atomicAdd(&g_hist[dst * N_REL + r], 1);
}

__global__ void k_scan1() {
    __shared__ int s[1024];
    int tid = threadIdx.x;
    int i = blockIdx.x * 1024 + tid;
    int v = (i < NKEY) ? g_hist[i] : 0;
    s[tid] = v;
    __syncthreads();
#pragma unroll
    for (int o = 1; o < 1024; o <<= 1) {
        int t = (tid >= o) ? s[tid - o] : 0;
        __syncthreads();
        s[tid] += t;
        __syncthreads();
    }
    if (i < NKEY) g_rowptr[i] = s[tid] - v;
    if (tid == 1023) g_aux[blockIdx.x] = s[1023];
}

__global__ void k_scan2() {
    __shared__ int s[1024];
    int tid = threadIdx.x;
    int v = (tid < NSCANBLK) ? g_aux[tid] : 0;
    s[tid] = v;
    __syncthreads();
#pragma unroll
    for (int o = 1; o < 1024; o <<= 1) {
        int t = (tid >= o) ? s[tid - o] : 0;
        __syncthreads();
        s[tid] += t;
        __syncthreads();
    }
    if (tid < NSCANBLK) g_auxs[tid] = s[tid] - v;
}

__global__ void k_scan3() {
    int i = blockIdx.x * blockDim.x + threadIdx.x;
    if (i < NKEY) {
        int v = g_rowptr[i] + g_auxs[i >> 10];
        g_rowptr[i] = v;
        g_cursor[i] = v;
    }
    if (i == 0) g_rowptr[NKEY] = N_EDGES;
}

__global__ void k_scatter_pos(const int* __restrict__ edge_index,
                              const int* __restrict__ edge_type) {
    int e = blockIdx.x * blockDim.x + threadIdx.x;
    if (e >= N_EDGES) return;
    int src = edge_index[e];
    int dst = edge_index[N_EDGES + e];
    int r   = edge_type[e];
    int pos = atomicAdd(&g_cursor[dst * N_REL + r], 1);
    g_esrc[pos] = src;
}

// ---------------- weights: [slot][o][k<=192] fp16 (pad k>=160 zero) ----------------
#define WT_N (NSLOT * OUT_CH * KW)   // 221184
__global__ void k_build_wt(const float* __restrict__ bases,
                           const float* __restrict__ comp,
                           const float* __restrict__ root_w) {
    int idx = blockIdx.x * blockDim.x + threadIdx.x;
    if (idx >= WT_N) return;
    int s   = idx / (OUT_CH * KW);
    int rem = idx - s * (OUT_CH * KW);
    int o   = rem / KW;
    int k   = rem - o * KW;
    float v = 0.f;
    if (k < FEAT) {
        if (s == 0) {
            v = root_w[k * OUT_CH + o];
        } else {
            int r = s - 1;
#pragma unroll
            for (int b = 0; b < N_BASES; ++b)
                v = fmaf(comp[r * N_BASES + b], bases[((size_t)b * FEAT + k) * OUT_CH + o], v);
        }
    }
    g_Wt[idx] = __float2half(v);
}

// ---------------- h build (fp16 only) ----------------
__global__ void k_build_h(const float* __restrict__ x,
                          const int* __restrict__ ntype,
                          const float* __restrict__ emb) {
    int i = blockIdx.x * blockDim.x + threadIdx.x;
    if (i >= N_NODES * FEAT) return;
    int n = i / FEAT;
    int f = i - n * FEAT;
    float v = (f < IN_CH) ? x[(size_t)n * IN_CH + f]
                          : emb[ntype[n] * TYPE_EMB + (f - IN_CH)];
    g_h16[(size_t)n * FEAT + f] = __float2half(v);
}

// ---------------- zgemm: Z[n][s*128..] = h[n] @ W_s  (A-resident, 9-slot loop) ----------------
// SMEM: [0,4) tmem | [8,16) mbar | A @1024: 6 x 16KB SW128 (2 m-tiles x 3 chunks)
//       B @99328: 2 bufs x 3 x 16KB
#define SA_OFF    1024
#define SB_OFF    (SA_OFF + 6 * 16384)     // 99328
#define ZG_SMEM   (SB_OFF + 2 * 49152)     // 197632

__global__ __launch_bounds__(256, 1)
void k_zgemm(int dummy) {
#if HAS_TCGEN05
    extern __shared__ char smem[];
    const uint32_t smem_base = smem_u32(smem);
    const int tid  = threadIdx.x;
    const int wid  = tid >> 5;
    const int lane = tid & 31;
    const int n0   = blockIdx.x * 256;

    if (tid == 0 && blockIdx.x == 0) g_mma_ok = 1;

    if (wid == 0) {
        TCGEN05_ALLOC(smem_base + 0, 256);
        TCGEN05_RELINQ();
    }
    if (tid == 0) MBARRIER_INIT(smem_base + 8, 1);
    __syncthreads();

    uint32_t tmem;
    asm volatile("ld.shared.b32 %0, [%1];" : "=r"(tmem) : "r"(smem_base));

    // ---- stage A (once): 6 blocks of 128x64 fp16, SW128 ----
#pragma unroll
    for (int p = 0; p < 24; ++p) {
        int q   = p * 256 + tid;          // 0..6143
        int blk = q >> 10;                // 0..5
        int qq  = q & 1023;
        int rw  = qq >> 3;                // 0..127
        int w16 = (qq & 7) * 16;
        int m   = blk / 3;
        int c   = blk - m * 3;
        int node = n0 + m * 128 + rw;
        int kb  = c * 128 + w16;
        uint32_t sz = (node < N_NODES && kb < 320) ? 16u : 0u;
        int na = (node < N_NODES) ? node : (N_NODES - 1);
        uint32_t off = (uint32_t)(rw * 128 + w16);
        uint32_t sw  = off ^ ((off >> 3) & 0x70);
        cp16(smem_base + SA_OFF + blk * 16384 + sw,
             (const char*)(g_h16 + (size_t)na * FEAT) + kb, sz);
    }
    // ---- stage B slot 0 into buf 0 ----
#define STAGE_B(s, buf) do { \
        _Pragma("unroll") \
        for (int p = 0; p < 12; ++p) { \
            int q   = p * 256 + tid;      /* 0..3071 */ \
            int c   = q >> 10; \
            int qq  = q & 1023; \
            int o   = qq >> 3; \
            int w16 = (qq & 7) * 16; \
            uint32_t off = (uint32_t)(o * 128 + w16); \
            uint32_t sw  = off ^ ((off >> 3) & 0x70); \
            const char* src = (const char*)(g_Wt + ((size_t)(s) * OUT_CH + o) * KW) + c * 128 + w16; \
            cp16(smem_base + SB_OFF + (uint32_t)(buf) * 49152 + c * 16384 + sw, src, 16u); \
        } \
    } while (0)

    STAGE_B(0, 0);
    CP_COMMIT();

    int phase = 0;
    for (int s = 0; s < NSLOT; ++s) {
        // prefetch next slot's B into the other buffer (its previous user, MMA s-1, is done)
        if (s + 1 < NSLOT) {
            STAGE_B(s + 1, (s + 1) & 1);
            CP_COMMIT();
            CP_WAIT1();        // B_s (and A) retired; B_{s+1} may still fly
        } else {
            CP_WAIT0();
        }
        __syncthreads();

        if (wid == 0) {
            asm volatile("fence.proxy.async.shared::cta;" ::: "memory");
            if (elect_one()) {
                uint32_t bb = smem_base + SB_OFF + (uint32_t)(s & 1) * 49152;
#pragma unroll
                for (int m = 0; m < 2; ++m) {
                    uint32_t d = tmem + (uint32_t)(m * 128);
#pragma unroll
                    for (int c = 0; c < 3; ++c) {
                        uint64_t dA = MAKE_SMEM_DESC(smem_base + SA_OFF + (m * 3 + c) * 16384);
                        uint64_t dB = MAKE_SMEM_DESC(bb + c * 16384);
#pragma unroll
                        for (int st = 0; st < 4; ++st)
                            mma_f16_ss(d, dA + st * 2, dB + st * 2, !(c == 0 && st == 0));
                    }
                }
                TCGEN05_COMMIT(smem_base + 8);
            }
        }
        MBARRIER_WAIT_PARITY(smem_base + 8, phase);
        phase ^= 1;
        TCGEN05_FENCE_AFTER();

        // ---- epilogue for slot s: fp32 -> fp16, store Z ----
        {
            int rsub = wid & 3;
            int c0   = (wid >> 2) * 64;
#pragma unroll
            for (int mh = 0; mh < 2; ++mh) {
                int node = n0 + mh * 128 + rsub * 32 + lane;
#pragma unroll
                for (int g = 0; g < 2; ++g) {
                    uint32_t regs[32];
                    TCGEN05_LD_32X32B_X32(regs, tmem + (uint32_t)(mh * 128 + c0 + g * 32));
                    TCGEN05_WAIT_LD();
                    if (node < N_NODES) {
                        uint32_t pk[16];
#pragma unroll
                        for (int j = 0; j < 16; ++j) {
                            __half2 h2 = __floats2half2_rn(__uint_as_float(regs[2 * j]),
                                                           __uint_as_float(regs[2 * j + 1]));
                            pk[j] = *reinterpret_cast<uint32_t*>(&h2);
                        }
                        uint4* zp = reinterpret_cast<uint4*>(
                            g_Z + (size_t)node * ZLEN + s * OUT_CH + c0 + g * 32);
                        zp[0] = make_uint4(pk[0], pk[1], pk[2], pk[3]);
                        zp[1] = make_uint4(pk[4], pk[5], pk[6], pk[7]);
                        zp[2] = make_uint4(pk[8], pk[9], pk[10], pk[11]);
                        zp[3] = make_uint4(pk[12], pk[13], pk[14], pk[15]);
                    }
                }
            }
        }
        TCGEN05_FENCE_BEFORE();
        __syncthreads();
    }
#undef STAGE_B

    if (tid == 0) MBARRIER_INVAL(smem_base + 8);
    __syncthreads();
    if (wid == 0) TCGEN05_DEALLOC(tmem, 256);
#else
    if (threadIdx.x == 0 && blockIdx.x == 0) g_mma_ok = 0;
#endif
}

// ---------------- fallback Z gemm (fp32 FMA; never runs when MMA ok) ----------------
__global__ __launch_bounds__(256, 2)
void k_z_fp32() {
    if (g_mma_ok) return;
    __shared__ float As[32][132];
    __shared__ float Bs[32][128];
    const int tid = threadIdx.x;
    const int n0  = blockIdx.x * 128;
    const int s   = blockIdx.y;
    const int ty  = tid >> 4;
    const int tx  = tid & 15;
    float acc[8][8];
#pragma unroll
    for (int i = 0; i < 8; ++i)
#pragma unroll
        for (int j = 0; j < 8; ++j) acc[i][j] = 0.f;

    for (int kt = 0; kt < 5; ++kt) {          // K = 160 = 5 x 32
        const int k0 = kt * 32;
        for (int q = tid; q < 128 * 32; q += 256) {
            int m = q >> 5, kk = q & 31;
            int node = n0 + m;
            As[kk][m] = (node < N_NODES) ? __half2float(g_h16[(size_t)node * FEAT + k0 + kk]) : 0.f;
        }
        for (int q = tid; q < 128 * 32; q += 256) {
            int o = q >> 5, kk = q & 31;
            Bs[kk][o] = __half2float(g_Wt[((size_t)s * OUT_CH + o) * KW + k0 + kk]);
        }
        __syncthreads();
#pragma unroll 8
        for (int kk = 0; kk < 32; ++kk) {
#pragma unroll
            for (int i = 0; i < 8; ++i)
#pragma unroll
                for (int j = 0; j < 8; ++j)
                    acc[i][j] = fmaf(As[kk][ty * 8 + i], Bs[kk][tx * 8 + j], acc[i][j]);
        }
        __syncthreads();
    }
#pragma unroll
    for (int i = 0; i < 8; ++i) {
        int node = n0 + ty * 8 + i;
        if (node >= N_NODES) continue;
        __half* zp = g_Z + (size_t)node * ZLEN + s * OUT_CH + tx * 8;
#pragma unroll
        for (int j = 0; j < 8; ++j) zp[j] = __float2half(acc[i][j]);
    }
}

// ---------------- final: warp per dst, gather Z, mean, bias, ReLU ----------------
__global__ __launch_bounds__(256)
void k_final(const float* __restrict__ bias, float* __restrict__ out) {
    int w    = (blockIdx.x * blockDim.x + threadIdx.x) >> 5;   // dst
    int lane = threadIdx.x & 31;
    if (w >= N_NODES) return;

    int rpv = 0;
    if (lane <= 8) rpv = g_rowptr[w * N_REL + lane];

    float acc[8] = {0.f, 0.f, 0.f, 0.f, 0.f, 0.f, 0.f, 0.f};
    // root term: Z slot 0
    if (lane < 16) {
        uint4 v = reinterpret_cast<const uint4*>(g_Z + (size_t)w * ZLEN)[lane];
        float2 f0 = __half22float2(*reinterpret_cast<__half2*>(&v.x));
        float2 f1 = __half22float2(*reinterpret_cast<__half2*>(&v.y));
        float2 f2 = __half22float2(*reinterpret_cast<__half2*>(&v.z));
        float2 f3 = __half22float2(*reinterpret_cast<__half2*>(&v.w));
        acc[0] = f0.x; acc[1] = f0.y; acc[2] = f1.x; acc[3] = f1.y;
        acc[4] = f2.x; acc[5] = f2.y; acc[6] = f3.x; acc[7] = f3.y;
    }

#pragma unroll
    for (int r = 0; r < N_REL; ++r) {
        int beg = __shfl_sync(0xFFFFFFFFu, rpv, r);
        int end = __shfl_sync(0xFFFFFFFFu, rpv, r + 1);
        float p[8] = {0.f, 0.f, 0.f, 0.f, 0.f, 0.f, 0.f, 0.f};
        for (int e = beg; e < end; ++e) {
            int src = g_esrc[e];
            if (lane < 16) {
                uint4 v = reinterpret_cast<const uint4*>(
                    g_Z + (size_t)src * ZLEN + (1 + r) * OUT_CH)[lane];
                float2 f0 = __half22float2(*reinterpret_cast<__half2*>(&v.x));
                float2 f1 = __half22float2(*reinterpret_cast<__half2*>(&v.y));
                float2 f2 = __half22float2(*reinterpret_cast<__half2*>(&v.z));
                float2 f3 = __half22float2(*reinterpret_cast<__half2*>(&v.w));
                p[0] += f0.x; p[1] += f0.y; p[2] += f1.x; p[3] += f1.y;
                p[4] += f2.x; p[5] += f2.y; p[6] += f3.x; p[7] += f3.y;
            }
        }
        float sc = 1.0f / fmaxf((float)(end - beg), 1.0f);
#pragma unroll
        for (int j = 0; j < 8; ++j) acc[j] += p[j] * sc;
    }

    if (lane < 16) {
        const float4* bp = reinterpret_cast<const float4*>(bias + lane * 8);
        float4 b0 = bp[0], b1 = bp[1];
        float4 o0, o1;
        o0.x = fmaxf(acc[0] + b0.x, 0.f);
        o0.y = fmaxf(acc[1] + b0.y, 0.f);
        o0.z = fmaxf(acc[2] + b0.z, 0.f);
        o0.w = fmaxf(acc[3] + b0.w, 0.f);
        o1.x = fmaxf(acc[4] + b1.x, 0.f);
        o1.y = fmaxf(acc[5] + b1.y, 0.f);
        o1.z = fmaxf(acc[6] + b1.z, 0.f);
        o1.w = fmaxf(acc[7] + b1.w, 0.f);
        float4* op = reinterpret_cast<float4*>(out + (size_t)w * OUT_CH + lane * 8);
        op[0] = o0;
        op[1] = o1;
    }
}

// ---------------- launch (stream-parallel DAG) ----------------
extern "C" void kernel_launch(void* const* d_in, const int* in_sizes, int n_in,
                              void* d_out, int out_size) {
    const float* x      = (const float*)d_in[0];
    const int*   ntype  = (const int*)  d_in[1];
    const int*   eidx   = (const int*)  d_in[2];
    const int*   etype  = (const int*)  d_in[3];
    const float* emb    = (const float*)d_in[4];
    const float* bases  = (const float*)d_in[5];
    const float* comp   = (const float*)d_in[6];
    const float* root_w = (const float*)d_in[7];
    const float* bias   = (const float*)d_in[8];
    float*       out    = (float*)d_out;

    static cudaStream_t s1 = nullptr, s2 = nullptr;
    static cudaEvent_t evRoot = nullptr, evW = nullptr, evZ = nullptr;
    if (!s1) {
        cudaStreamCreateWithFlags(&s1, cudaStreamNonBlocking);
        cudaStreamCreateWithFlags(&s2, cudaStreamNonBlocking);
        cudaEventCreateWithFlags(&evRoot, cudaEventDisableTiming);
        cudaEventCreateWithFlags(&evW, cudaEventDisableTiming);
        cudaEventCreateWithFlags(&evZ, cudaEventDisableTiming);
        cudaFuncSetAttribute(k_zgemm, cudaFuncAttributeMaxDynamicSharedMemorySize, ZG_SMEM);
    }

    cudaEventRecord(evRoot, 0);
    cudaStreamWaitEvent(s1, evRoot, 0);
    cudaStreamWaitEvent(s2, evRoot, 0);

    // s2: weight table
    k_build_wt<<<(WT_N + 255) / 256, 256, 0, s2>>>(bases, comp, root_w);
    cudaEventRecord(evW, s2);

    // s1: h build -> zgemm (needs Wt) -> fallback
    k_build_h<<<(N_NODES * FEAT + 255) / 256, 256, 0, s1>>>(x, ntype, emb);
    cudaStreamWaitEvent(s1, evW, 0);
    k_zgemm<<<NTILE2, 256, ZG_SMEM, s1>>>(0);
    {
        dim3 g((N_NODES + 127) / 128, NSLOT);
        k_z_fp32<<<g, 256, 0, s1>>>();
    }
    cudaEventRecord(evZ, s1);

    // main: CSR chain (independent of Z)
    k_zero_hist<<<(NKEY + 255) / 256, 256>>>();
    k_hist<<<(N_EDGES + 255) / 256, 256>>>(eidx, etype);
    k_scan1<<<NSCANBLK, 1024>>>();
    k_scan2<<<1, 1024>>>();
    k_scan3<<<(NKEY + 255) / 256, 256>>>();
    k_scatter_pos<<<(N_EDGES + 255) / 256, 256>>>(eidx, etype);

    // join Z before the fused gather/epilogue
    cudaStreamWaitEvent(0, evZ, 0);
    k_final<<<(N_NODES * 32 + 255) / 256, 256>>>(bias, out);
}

// round 15
// speedup vs baseline: 1.2539x; 1.2539x over previous
#include <cuda_runtime.h>
#include <cuda_bf16.h>
#include <cuda_fp16.h>
#include <cstdint>

#define N_NODES 100000
#define N_EDGES 1600000
#define IN_CH   128
#define TYPE_EMB 32
#define FEAT    160
#define OUT_CH  128
#define N_REL   8
#define N_BASES 8
#define KTOT    1440             // FEAT * 9 logical
#define KPAD    1472             // 23 * 64
#define KCH     64
#define NCHUNK  23
#define A16LEN  1312             // 8 relation slots * 160 + 32 pad (pad never read)
#define NKEY    (N_NODES * N_REL)        // 800000
#define NSCANBLK ((NKEY + 1023) / 1024)  // 782
#define NTILE2  ((N_NODES + 255) / 256)  // 391

// Arch-feature gate: tcgen05 only exists on the 'a' targets.
#if defined(__CUDA_ARCH_FEAT_SM103_ALL) || defined(__CUDA_ARCH_FEAT_SM100_ALL) || \
    defined(__CUDA_ARCH_FEAT_SM101_ALL) || \
    (defined(__CUDA_ARCH_SPECIFIC__) && (__CUDA_ARCH_SPECIFIC__ >= 1000))
#define HAS_TCGEN05 1
#else
#define HAS_TCGEN05 0
#endif

// ---------------- device scratch ----------------
__device__ __half g_h16[(size_t)N_NODES * FEAT];       // fp16 h (32MB, L2-resident)
__device__ __half g_A16[(size_t)N_NODES * A16LEN];     // fp16 relation means (slots 1..8)
__device__ float  g_W[KTOT * OUT_CH];                  // fp32 (fallback path)
__device__ __half g_Bh[OUT_CH * KPAD];                 // W^T fp16, [o][k]
__device__ int g_mma_ok;

// CSR scratch
__device__ int g_hist[NKEY];
__device__ int g_rowptr[NKEY + 1];
__device__ int g_rank[N_EDGES];
__device__ int g_aux[NSCANBLK];
__device__ int g_auxs[NSCANBLK];
__device__ int g_esrc[N_EDGES];

// ================= PTX helpers =================
__device__ __forceinline__ uint32_t smem_u32(const void* p) {
    uint32_t a;
    asm("{ .reg .u64 t; cvta.to.shared.u64 t, %1; cvt.u32.u64 %0, t; }" : "=r"(a) : "l"(p));
    return a;
}
__device__ __forceinline__ void cp16(uint32_t smem, const void* g, uint32_t sz) {
    asm volatile("cp.async.cg.shared.global [%0], [%1], 16, %2;"
                 :: "r"(smem), "l"(g), "r"(sz) : "memory");
}
#define CP_COMMIT() asm volatile("cp.async.commit_group;" ::: "memory")
#define CP_WAIT2()  asm volatile("cp.async.wait_group 2;" ::: "memory")

#define MBARRIER_INIT(addr, cnt) \
    asm volatile("mbarrier.init.shared.b64 [%0], %1;" :: "r"((uint32_t)(addr)), "r"((uint32_t)(cnt)) : "memory")
#define MBARRIER_INVAL(addr) \
    asm volatile("mbarrier.inval.shared.b64 [%0];" :: "r"((uint32_t)(addr)) : "memory")
#define MBARRIER_WAIT_PARITY(mbar_smem_addr, phase_parity) do { \
    uint32_t _mbar = (uint32_t)(mbar_smem_addr); \
    uint32_t _parity = (uint32_t)(phase_parity); \
    uint32_t _done; \
    asm volatile( \
        "{\n\t.reg .pred p;\n\t" \
        "mbarrier.try_wait.parity.acquire.cta.shared::cta.b64 p, [%1], %2;\n\t" \
        "selp.b32 %0, 1, 0, p;\n\t}" \
        : "=r"(_done) : "r"(_mbar), "r"(_parity) : "memory"); \
    if (!_done) { \
        asm volatile( \
            "{\n\t.reg .pred P1;\n\t" \
            "WAIT_LOOP_%=:\n\t" \
            "mbarrier.try_wait.parity.acquire.cta.shared::cta.b64 P1, [%0], %1, 0x989680;\n\t" \
            "@P1 bra.uni WAIT_DONE_%=;\n\t" \
            "bra.uni WAIT_LOOP_%=;\n\t" \
            "WAIT_DONE_%=:\n\t}" \
            :: "r"(_mbar), "r"(_parity) : "memory"); \
    } \
} while(0)

#if HAS_TCGEN05
__device__ __forceinline__ uint32_t elect_one() {
    uint32_t pred;
    asm volatile("{\n\t.reg .pred p;\n\telect.sync _|p, 0xFFFFFFFF;\n\tselp.b32 %0, 1, 0, p;\n\t}" : "=r"(pred));
    return pred;
}
#define TCGEN05_ALLOC(smem_addr, nCols) \
    asm volatile("tcgen05.alloc.cta_group::1.sync.aligned.shared::cta.b32 [%0], %1;" \
        :: "r"((uint32_t)(smem_addr)), "r"((uint32_t)(nCols)) : "memory")
#define TCGEN05_DEALLOC(tmem_addr, nCols) \
    asm volatile("tcgen05.dealloc.cta_group::1.sync.aligned.b32 %0, %1;" :: "r"(tmem_addr), "r"((uint32_t)(nCols)))
#define TCGEN05_RELINQ() \
    asm volatile("tcgen05.relinquish_alloc_permit.cta_group::1.sync.aligned;")
#define TCGEN05_COMMIT(mbar) \
    asm volatile("tcgen05.commit.cta_group::1.mbarrier::arrive::one.shared::cluster.b64 [%0];" \
        :: "r"((uint32_t)(mbar)) : "memory")
#define TCGEN05_FENCE_AFTER()  asm volatile("tcgen05.fence::after_thread_sync;" ::: "memory")
#define TCGEN05_FENCE_BEFORE() asm volatile("tcgen05.fence::before_thread_sync;" ::: "memory")
#define TCGEN05_WAIT_LD() asm volatile("tcgen05.wait::ld.sync.aligned;" ::: "memory")
#define TCGEN05_LD_32X32B_X32(r, tmem_addr) \
    asm volatile( \
        "tcgen05.ld.sync.aligned.32x32b.x32.b32 " \
        "{%0, %1, %2, %3, %4, %5, %6, %7, " \
        " %8, %9, %10, %11, %12, %13, %14, %15, " \
        " %16, %17, %18, %19, %20, %21, %22, %23, " \
        " %24, %25, %26, %27, %28, %29, %30, %31}, [%32];" \
        : "=r"((r)[0]),  "=r"((r)[1]),  "=r"((r)[2]),  "=r"((r)[3]), \
          "=r"((r)[4]),  "=r"((r)[5]),  "=r"((r)[6]),  "=r"((r)[7]), \
          "=r"((r)[8]),  "=r"((r)[9]),  "=r"((r)[10]), "=r"((r)[11]), \
          "=r"((r)[12]), "=r"((r)[13]), "=r"((r)[14]), "=r"((r)[15]), \
          "=r"((r)[16]), "=r"((r)[17]), "=r"((r)[18]), "=r"((r)[19]), \
          "=r"((r)[20]), "=r"((r)[21]), "=r"((r)[22]), "=r"((r)[23]), \
          "=r"((r)[24]), "=r"((r)[25]), "=r"((r)[26]), "=r"((r)[27]), \
          "=r"((r)[28]), "=r"((r)[29]), "=r"((r)[30]), "=r"((r)[31]) \
        : "r"(tmem_addr))

static constexpr uint64_t SMEM_DESC_BASE_SW128 =
    (uint64_t(2)  << 61) | (uint64_t(1) << 46) | (uint64_t(64) << 32) | (uint64_t(1) << 16);
#define MAKE_SMEM_DESC(base_addr) (SMEM_DESC_BASE_SW128 | ((uint64_t)((base_addr) >> 4) & 0x3FFF))

// idesc: dtype=F32, atype=F16, btype=F16, N=128, M=128 (kind::f16)
#define MMA_IDESC 0x8200010u

__device__ __forceinline__ void mma_f16_ss(uint32_t d, uint64_t a_desc, uint64_t b_desc, bool acc) {
    uint32_t en = acc ? 1u : 0u;
    asm volatile(
        "{\n\t.reg .pred p;\n\t"
        "setp.ne.u32 p, %5, 0;\n\t"
        "tcgen05.mma.cta_group::1.kind::f16 [%0], %1, %2, %3, {%4, %4, %4, %4}, p;\n\t"
        "}"
        :: "r"(d), "l"(a_desc), "l"(b_desc), "r"(MMA_IDESC), "r"(0u), "r"(en)
        : "memory");
}
#endif  // HAS_TCGEN05

// ---------------- CSR pipeline ----------------
__global__ void k_zero_hist() {
    int i = blockIdx.x * blockDim.x + threadIdx.x;
    if (i < NKEY) g_hist[i] = 0;
}

// hist + rank (rank = order within bucket)
__global__ void k_hist(const int* __restrict__ edge_index,
                       const int* __restrict__ edge_type) {
    int e = blockIdx.x * blockDim.x + threadIdx.x;
    if (e >= N_EDGES) return;
    int dst = edge_index[N_EDGES + e];
    int r   = edge_type[e];
    g_rank[e] = atomicAdd(&g_hist[dst * N_REL + r], 1);
}

__global__ void k_scan1() {
    __shared__ int s[1024];
    int tid = threadIdx.x;
    int i = blockIdx.x * 1024 + tid;
    int v = (i < NKEY) ? g_hist[i] : 0;
    s[tid] = v;
    __syncthreads();
#pragma unroll
    for (int o = 1; o < 1024; o <<= 1) {
        int t = (tid >= o) ? s[tid - o] : 0;
        __syncthreads();
        s[tid] += t;
        __syncthreads();
    }
    if (i < NKEY) g_rowptr[i] = s[tid] - v;
    if (tid == 1023) g_aux[blockIdx.x] = s[1023];
}

__global__ void k_scan2() {
    __shared__ int s[1024];
    int tid = threadIdx.x;
    int v = (tid < NSCANBLK) ? g_aux[tid] : 0;
    s[tid] = v;
    __syncthreads();
#pragma unroll
    for (int o = 1; o < 1024; o <<= 1) {
        int t = (tid >= o) ? s[tid - o] : 0;
        __syncthreads();
        s[tid] += t;
        __syncthreads();
    }
    if (tid < NSCANBLK) g_auxs[tid] = s[tid] - v;
}

__global__ void k_scan3() {
    int i = blockIdx.x * blockDim.x + threadIdx.x;
    if (i < NKEY) g_rowptr[i] = g_rowptr[i] + g_auxs[i >> 10];
    if (i == 0) g_rowptr[NKEY] = N_EDGES;
}

// atomic-free scatter: pos = rowptr[key] + rank[e]
__global__ void k_scatter_pos(const int* __restrict__ edge_index,
                              const int* __restrict__ edge_type) {
    int e = blockIdx.x * blockDim.x + threadIdx.x;
    if (e >= N_EDGES) return;
    int src = edge_index[e];
    int dst = edge_index[N_EDGES + e];
    int r   = edge_type[e];
    g_esrc[g_rowptr[dst * N_REL + r] + g_rank[e]] = src;
}

// ---------------- aggregation: grid-stride warps, LDG.128 gather, unroll-2 ----------------
#define AGG_BLOCKS 4096
__global__ __launch_bounds__(256)
void k_aggregate() {
    int lane   = threadIdx.x & 31;
    int wfirst = (blockIdx.x * blockDim.x + threadIdx.x) >> 5;
    int wstep  = (AGG_BLOCKS * 256) >> 5;
    if (lane >= 20) return;

    for (int w = wfirst; w < NKEY; w += wstep) {
        int beg = g_rowptr[w];
        int end = g_rowptr[w + 1];

        float acc[8];
#pragma unroll
        for (int j = 0; j < 8; ++j) acc[j] = 0.f;

        int e = beg;
        for (; e + 1 < end; e += 2) {
            int s0 = g_esrc[e];
            int s1 = g_esrc[e + 1];
            uint4 v0 = reinterpret_cast<const uint4*>(g_h16 + (size_t)s0 * FEAT)[lane];
            uint4 v1 = reinterpret_cast<const uint4*>(g_h16 + (size_t)s1 * FEAT)[lane];
            float2 a0 = __half22float2(*reinterpret_cast<__half2*>(&v0.x));
            float2 a1 = __half22float2(*reinterpret_cast<__half2*>(&v0.y));
            float2 a2 = __half22float2(*reinterpret_cast<__half2*>(&v0.z));
            float2 a3 = __half22float2(*reinterpret_cast<__half2*>(&v0.w));
            float2 b0 = __half22float2(*reinterpret_cast<__half2*>(&v1.x));
            float2 b1 = __half22float2(*reinterpret_cast<__half2*>(&v1.y));
            float2 b2 = __half22float2(*reinterpret_cast<__half2*>(&v1.z));
            float2 b3 = __half22float2(*reinterpret_cast<__half2*>(&v1.w));
            acc[0] += a0.x + b0.x; acc[1] += a0.y + b0.y;
            acc[2] += a1.x + b1.x; acc[3] += a1.y + b1.y;
            acc[4] += a2.x + b2.x; acc[5] += a2.y + b2.y;
            acc[6] += a3.x + b3.x; acc[7] += a3.y + b3.y;
        }
        if (e < end) {
            int s0 = g_esrc[e];
            uint4 v0 = reinterpret_cast<const uint4*>(g_h16 + (size_t)s0 * FEAT)[lane];
            float2 a0 = __half22float2(*reinterpret_cast<__half2*>(&v0.x));
            float2 a1 = __half22float2(*reinterpret_cast<__half2*>(&v0.y));
            float2 a2 = __half22float2(*reinterpret_cast<__half2*>(&v0.z));
            float2 a3 = __half22float2(*reinterpret_cast<__half2*>(&v0.w));
            acc[0] += a0.x; acc[1] += a0.y;
            acc[2] += a1.x; acc[3] += a1.y;
            acc[4] += a2.x; acc[5] += a2.y;
            acc[6] += a3.x; acc[7] += a3.y;
        }
        float sc = 1.0f / fmaxf((float)(end - beg), 1.0f);

        int dst = w >> 3;
        int r   = w & 7;
        __half2 o0 = __floats2half2_rn(acc[0] * sc, acc[1] * sc);
        __half2 o1 = __floats2half2_rn(acc[2] * sc, acc[3] * sc);
        __half2 o2 = __floats2half2_rn(acc[4] * sc, acc[5] * sc);
        __half2 o3 = __floats2half2_rn(acc[6] * sc, acc[7] * sc);
        uint4 ov;
        ov.x = *reinterpret_cast<uint32_t*>(&o0);
        ov.y = *reinterpret_cast<uint32_t*>(&o1);
        ov.z = *reinterpret_cast<uint32_t*>(&o2);
        ov.w = *reinterpret_cast<uint32_t*>(&o3);
        reinterpret_cast<uint4*>(g_A16 + (size_t)dst * A16LEN + (size_t)r * FEAT)[lane] = ov;
    }
}

// ---------------- weights (fp32 + fp16) ----------------
__global__ void k_build_wt(const float* __restrict__ bases,
                           const float* __restrict__ comp,
                           const float* __restrict__ root_w) {
    int idx = blockIdx.x * blockDim.x + threadIdx.x;
    if (idx >= OUT_CH * KPAD) return;
    int o = idx / KPAD;
    int k = idx - o * KPAD;
    float v = 0.f;
    if (k < FEAT) {
        v = root_w[k * OUT_CH + o];
    } else if (k < KTOT) {
        int r = k / FEAT - 1;
        int f = k - (r + 1) * FEAT;
#pragma unroll
        for (int b = 0; b < N_BASES; ++b)
            v = fmaf(comp[r * N_BASES + b], bases[((size_t)b * FEAT + f) * OUT_CH + o], v);
    }
    g_Bh[idx] = __float2half(v);
    if (k < KTOT) g_W[k * OUT_CH + o] = v;
}

// ---------------- h build (fp16 only) ----------------
__global__ void k_build_h(const float* __restrict__ x,
                          const int* __restrict__ ntype,
                          const float* __restrict__ emb) {
    int i = blockIdx.x * blockDim.x + threadIdx.x;
    if (i >= N_NODES * FEAT) return;
    int n = i / FEAT;
    int f = i - n * FEAT;
    float v = (f < IN_CH) ? x[(size_t)n * IN_CH + f]
                          : emb[ntype[n] * TYPE_EMB + (f - IN_CH)];
    g_h16[(size_t)n * FEAT + f] = __float2half(v);
}

// ---------------- tcgen05 fp16 GEMM: M=256 tiles, 3-stage cp.async pipeline ----------------
// Stage (48KB): A[32K] | B[16K]
#define STAGE_B   49152
#define SA_OFF    0
#define SB_OFF    32768
#define ST_OFF    1024
#define GEMM_SMEM (ST_OFF + 3 * STAGE_B)   // 148480

__global__ __launch_bounds__(256, 1)
void k_gemm_mma(const float* __restrict__ bias, float* __restrict__ out) {
#if HAS_TCGEN05
    extern __shared__ char smem[];
    const uint32_t smem_base = smem_u32(smem);
    const int tid  = threadIdx.x;
    const int wid  = tid >> 5;
    const int lane = tid & 31;
    const int n0   = blockIdx.x * 256;

    if (tid == 0 && blockIdx.x == 0) g_mma_ok = 1;

    float* sBias = reinterpret_cast<float*>(smem + 64);
    if (wid == 0) {
        TCGEN05_ALLOC(smem_base + 0, 256);
        TCGEN05_RELINQ();
    }
    if (tid == 0) {
        MBARRIER_INIT(smem_base + 8, 1);
        MBARRIER_INIT(smem_base + 16, 1);
        MBARRIER_INIT(smem_base + 24, 1);
    }
    if (tid < 128) sBias[tid] = bias[tid];
    __syncthreads();

    uint32_t tmem;
    asm volatile("ld.shared.b32 %0, [%1];" : "=r"(tmem) : "r"(smem_base));

    // A source: bytes [0,320) of the logical 2944-byte K-row come from g_h16,
    // bytes [320,2880) from g_A16 (relation means), bytes >=2880 are zero pad.
#define STAGE_CHUNK(c, sb) do { \
        const uint32_t stb = smem_base + ST_OFF + (uint32_t)(sb) * STAGE_B; \
        const int kb0 = (c) * 128; \
        _Pragma("unroll") \
        for (int p = 0; p < 8; ++p) { \
            int q   = p * 256 + tid; \
            int row = q >> 3; \
            int w16 = (q & 7) * 16; \
            int kb  = kb0 + w16; \
            int node = n0 + row; \
            uint32_t sz = (node < N_NODES && kb < 2880) ? 16u : 0u; \
            int na = (node < N_NODES) ? node : (N_NODES - 1); \
            const char* pa = (kb < 320) \
                ? ((const char*)(g_h16 + (size_t)na * FEAT) + kb) \
                : ((const char*)(g_A16 + (size_t)na * A16LEN) + (kb - 320)); \
            uint32_t off = (uint32_t)(row * 128 + w16); \
            uint32_t sw  = off ^ ((off >> 3) & 0x70); \
            cp16(stb + SA_OFF + sw, pa, sz); \
        } \
        _Pragma("unroll") \
        for (int p = 0; p < 2; ++p) { \
            int q   = p * 256 + tid; \
            int row = q >> 2; \
            int w16 = (q & 3) * 32; \
            uint32_t off = (uint32_t)(row * 128 + w16); \
            uint32_t sw0 = off ^ ((off >> 3) & 0x70); \
            uint32_t off1 = off + 16; \
            uint32_t sw1 = off1 ^ ((off1 >> 3) & 0x70); \
            const char* pb = (const char*)(g_Bh + (size_t)row * KPAD) + kb0 + w16; \
            cp16(stb + SB_OFF + sw0, pb, 16u); \
            cp16(stb + SB_OFF + sw1, pb + 16, 16u); \
        } \
    } while (0)

    int ph[3] = {0, 0, 0};

    STAGE_CHUNK(0, 0); CP_COMMIT();
    STAGE_CHUNK(1, 1); CP_COMMIT();

    for (int i = 0; i < NCHUNK; ++i) {
        int c2 = i + 2;
        if (c2 < NCHUNK) {
            int b2 = c2 % 3;
            if (i >= 1) {
                MBARRIER_WAIT_PARITY(smem_base + 8 + (uint32_t)b2 * 8, ph[b2]);
                ph[b2] ^= 1;
            }
            STAGE_CHUNK(c2, b2);
        }
        CP_COMMIT();
        CP_WAIT2();
        __syncthreads();

        if (wid == 0) {
            asm volatile("fence.proxy.async.shared::cta;" ::: "memory");
            if (elect_one()) {
                int b = i % 3;
                const uint32_t stb = smem_base + ST_OFF + (uint32_t)b * STAGE_B;
                uint64_t dB = MAKE_SMEM_DESC(stb + SB_OFF);
#pragma unroll
                for (int m = 0; m < 2; ++m) {
                    uint64_t dA = MAKE_SMEM_DESC(stb + SA_OFF + m * 16384);
                    uint32_t d  = tmem + (uint32_t)(m * 128);
#pragma unroll
                    for (int s = 0; s < 4; ++s)
                        mma_f16_ss(d, dA + s * 2, dB + s * 2, (i > 0) || (s > 0));
                }
                TCGEN05_COMMIT(smem_base + 8 + (uint32_t)b * 8);
            }
        }
    }
#undef STAGE_CHUNK

    MBARRIER_WAIT_PARITY(smem_base + 8,  ph[0]);
    MBARRIER_WAIT_PARITY(smem_base + 16, ph[1]);
    MBARRIER_WAIT_PARITY(smem_base + 24, ph[2]);
    TCGEN05_FENCE_AFTER();

    // ---- epilogue: two M-halves ----
    {
        int rsub = wid & 3;
        int c0   = (wid >> 2) * 64;
#pragma unroll
        for (int mh = 0; mh < 2; ++mh) {
            int node = n0 + mh * 128 + rsub * 32 + lane;
#pragma unroll
            for (int g = 0; g < 2; ++g) {
                uint32_t regs[32];
                TCGEN05_LD_32X32B_X32(regs, tmem + (uint32_t)(mh * 128 + c0 + g * 32));
                TCGEN05_WAIT_LD();
                if (node < N_NODES) {
                    float* op = out + (size_t)node * OUT_CH + c0 + g * 32;
#pragma unroll
                    for (int j4 = 0; j4 < 8; ++j4) {
                        float4 o;
                        o.x = fmaxf(__uint_as_float(regs[j4 * 4 + 0]) + sBias[c0 + g * 32 + j4 * 4 + 0], 0.f);
                        o.y = fmaxf(__uint_as_float(regs[j4 * 4 + 1]) + sBias[c0 + g * 32 + j4 * 4 + 1], 0.f);
                        o.z = fmaxf(__uint_as_float(regs[j4 * 4 + 2]) + sBias[c0 + g * 32 + j4 * 4 + 2], 0.f);
                        o.w = fmaxf(__uint_as_float(regs[j4 * 4 + 3]) + sBias[c0 + g * 32 + j4 * 4 + 3], 0.f);
                        *reinterpret_cast<float4*>(op + j4 * 4) = o;
                    }
                }
            }
        }
    }
    TCGEN05_FENCE_BEFORE();
    __syncthreads();
    if (tid == 0) {
        MBARRIER_INVAL(smem_base + 8);
        MBARRIER_INVAL(smem_base + 16);
        MBARRIER_INVAL(smem_base + 24);
    }
    __syncthreads();
    if (wid == 0) TCGEN05_DEALLOC(tmem, 256);
#else
    if (threadIdx.x == 0 && blockIdx.x == 0) g_mma_ok = 0;
#endif
}

// ---------------- fp32 fallback GEMM (grid-stride; cheap early exit) ----------------
#define BM 128
#define BK 32
#define FB_BLOCKS 296

__global__ __launch_bounds__(256, 2)
void k_gemm_fp32(const float* __restrict__ bias, float* __restrict__ out) {
    if (g_mma_ok) return;

    __shared__ float As[BK][BM + 4];
    __shared__ float Bs[BK][OUT_CH];

    const int tid = threadIdx.x;
    const int ty  = tid >> 4;
    const int tx  = tid & 15;

    for (int tile = blockIdx.x; tile < (N_NODES + BM - 1) / BM; tile += FB_BLOCKS) {
        const int n0 = tile * BM;
        float bb[8];
#pragma unroll
        for (int j = 0; j < 8; ++j) bb[j] = bias[tx * 8 + j];
        float acc[8][8];
#pragma unroll
        for (int i = 0; i < 8; ++i)
#pragma unroll
            for (int j = 0; j < 8; ++j) acc[i][j] = 0.f;

        for (int kt = 0; kt < KTOT / BK; ++kt) {
            const int k0 = kt * BK;
#pragma unroll
            for (int p = 0; p < 4; ++p) {
                int q = p * 256 + tid;
                int m = q >> 3;
                int kq = (q & 7) * 4;
                int node = n0 + m;
#pragma unroll
                for (int z = 0; z < 4; ++z) {
                    int k = k0 + kq + z;
                    float v = 0.f;
                    if (node < N_NODES)
                        v = (k < FEAT) ? __half2float(g_h16[(size_t)node * FEAT + k])
                                       : __half2float(g_A16[(size_t)node * A16LEN + (k - FEAT)]);
                    As[kq + z][m] = v;
                }
            }
#pragma unroll
            for (int p = 0; p < 4; ++p) {
                int q = p * 256 + tid;
                int kI = q >> 5;
                int n4 = (q & 31) * 4;
                *reinterpret_cast<float4*>(&Bs[kI][n4]) =
                    *reinterpret_cast<const float4*>(g_W + (size_t)(k0 + kI) * OUT_CH + n4);
            }
            __syncthreads();
#pragma unroll 8
            for (int kk = 0; kk < BK; ++kk) {
                float4 a0 = *reinterpret_cast<const float4*>(&As[kk][ty * 8]);
                float4 a1 = *reinterpret_cast<const float4*>(&As[kk][ty * 8 + 4]);
                float4 b0 = *reinterpret_cast<const float4*>(&Bs[kk][tx * 8]);
                float4 b1 = *reinterpret_cast<const float4*>(&Bs[kk][tx * 8 + 4]);
                float a[8] = {a0.x, a0.y, a0.z, a0.w, a1.x, a1.y, a1.z, a1.w};
                float b[8] = {b0.x, b0.y, b0.z, b0.w, b1.x, b1.y, b1.z, b1.w};
#pragma unroll
                for (int i = 0; i < 8; ++i)
#pragma unroll
                    for (int j = 0; j < 8; ++j)
                        acc[i][j] = fmaf(a[i], b[j], acc[i][j]);
            }
            __syncthreads();
        }
#pragma unroll
        for (int i = 0; i < 8; ++i) {
            int node = n0 + ty * 8 + i;
            if (node >= N_NODES) continue;
            float* op = out + (size_t)node * OUT_CH + tx * 8;
#pragma unroll
            for (int j = 0; j < 8; ++j)
                op[j] = fmaxf(acc[i][j] + bb[j], 0.f);
        }
        __syncthreads();
    }
}

// ---------------- launch (stream-parallel DAG, capture-fork pattern) ----------------
extern "C" void kernel_launch(void* const* d_in, const int* in_sizes, int n_in,
                              void* d_out, int out_size) {
    const float* x      = (const float*)d_in[0];
    const int*   ntype  = (const int*)  d_in[1];
    const int*   eidx   = (const int*)  d_in[2];
    const int*   etype  = (const int*)  d_in[3];
    const float* emb    = (const float*)d_in[4];
    const float* bases  = (const float*)d_in[5];
    const float* comp   = (const float*)d_in[6];
    const float* root_w = (const float*)d_in[7];
    const float* bias   = (const float*)d_in[8];
    float*       out    = (float*)d_out;

    static cudaStream_t s1 = nullptr, s2 = nullptr;
    static cudaEvent_t evRoot = nullptr, evH = nullptr, evW = nullptr;
    if (!s1) {
        cudaStreamCreateWithFlags(&s1, cudaStreamNonBlocking);
        cudaStreamCreateWithFlags(&s2, cudaStreamNonBlocking);
        cudaEventCreateWithFlags(&evRoot, cudaEventDisableTiming);
        cudaEventCreateWithFlags(&evH, cudaEventDisableTiming);
        cudaEventCreateWithFlags(&evW, cudaEventDisableTiming);
        cudaFuncSetAttribute(k_gemm_mma, cudaFuncAttributeMaxDynamicSharedMemorySize, GEMM_SMEM);
    }

    // fork side streams off the capture (default) stream
    cudaEventRecord(evRoot, 0);
    cudaStreamWaitEvent(s1, evRoot, 0);
    cudaStreamWaitEvent(s2, evRoot, 0);

    // side stream 1: h build (fp16)
    k_build_h<<<(N_NODES * FEAT + 255) / 256, 256, 0, s1>>>(x, ntype, emb);
    cudaEventRecord(evH, s1);

    // side stream 2: weight build
    k_build_wt<<<(OUT_CH * KPAD + 255) / 256, 256, 0, s2>>>(bases, comp, root_w);
    cudaEventRecord(evW, s2);

    // main stream: CSR chain (rank-based)
    k_zero_hist<<<(NKEY + 255) / 256, 256>>>();
    k_hist<<<(N_EDGES + 255) / 256, 256>>>(eidx, etype);
    k_scan1<<<NSCANBLK, 1024>>>();
    k_scan2<<<1, 1024>>>();
    k_scan3<<<(NKEY + 255) / 256, 256>>>();
    k_scatter_pos<<<(N_EDGES + 255) / 256, 256>>>(eidx, etype);

    // join h-build before aggregation
    cudaStreamWaitEvent(0, evH, 0);
    k_aggregate<<<AGG_BLOCKS, 256>>>();

    // join weight build before GEMM
    cudaStreamWaitEvent(0, evW, 0);
    k_gemm_mma<<<NTILE2, 256, GEMM_SMEM>>>(bias, out);
    k_gemm_fp32<<<FB_BLOCKS, 256>>>(bias, out);
}